// round 1
// baseline (speedup 1.0000x reference)
#include <cuda_runtime.h>
#include <math.h>

#define NB 16
#define NC 256
#define HH 56
#define WW 56
#define PLANE (HH*WW)
#define NPLANES (NB*NC)

// scratch (static device globals; no allocation)
__device__ float g_xfuse[NPLANES * PLANE];   // 51.4 MB
__device__ float g_pooled[NB * 49 * NC];     // [B][pos][C]
__device__ float g_wdyn[NB * 49 * NC];       // [B][pos][C]
__device__ float g_bdyn[NB * NC];            // [B][C]
__device__ float g_pw1T[256 * 64];           // [k][o]
__device__ float g_pw2T[64 * 1024];          // [k][oc]
__device__ float g_w1T[49 * 1024];           // [pos][g*C+c]

// ---------------------------------------------------------------------------
// Kernel 0: transpose small weight matrices so the MLP kernel reads coalesced
// ---------------------------------------------------------------------------
__global__ void k_transpose(const float* __restrict__ pw1,
                            const float* __restrict__ pw2,
                            const float* __restrict__ w1) {
    int i = blockIdx.x * 256 + threadIdx.x;
    if (i < 16384) {                       // pw1 [64,256] -> [256,64]
        int k = i >> 6, o = i & 63;
        g_pw1T[i] = pw1[o * 256 + k];
    }
    int j = i - 16384;
    if (j >= 0 && j < 65536) {             // pw2 [1024,64] -> [64,1024]
        int k = j >> 10, oc = j & 1023;
        g_pw2T[j] = pw2[oc * 64 + k];
    }
    int l = i - (16384 + 65536);
    if (l >= 0 && l < 49 * 1024) {         // weight1 [G*C,49] -> [49,G*C]
        int pos = l / 1024, gc = l & 1023;
        g_w1T[l] = w1[gc * 49 + pos];
    }
}

// ---------------------------------------------------------------------------
// Kernel 1: fused dw3x3+BN (x2), relu6 gate, x_fuse, and 7x7 block-mean pool
// One block per (b,c) plane. 392 compute threads = 56 rows x 7 groups of 8.
// ---------------------------------------------------------------------------
__global__ __launch_bounds__(448) void k_fuse(
    const float* __restrict__ x1,
    const float* __restrict__ dw1_w, const float* __restrict__ dw1_g,
    const float* __restrict__ dw1_b, const float* __restrict__ dw1_m,
    const float* __restrict__ dw1_v,
    const float* __restrict__ dw2_w, const float* __restrict__ dw2_g,
    const float* __restrict__ dw2_b, const float* __restrict__ dw2_m,
    const float* __restrict__ dw2_v) {
    __shared__ float s[58 * 60];          // padded plane (halo=1), stride 60
    __shared__ float partial[56 * 7];

    const int blk = blockIdx.x;
    const int b = blk >> 8, c = blk & 255;
    const float* __restrict__ xp = x1 + (size_t)blk * PLANE;
    const int tid = threadIdx.x;

    // load plane with zero halo
    for (int i = tid; i < 58 * 60; i += 448) {
        int r = i / 60, cc = i - r * 60;
        float v = 0.f;
        if (cc < 58) {
            int gr = r - 1, gc = cc - 1;
            if ((unsigned)gr < 56u && (unsigned)gc < 56u) v = xp[gr * 56 + gc];
        }
        s[i] = v;
    }

    // fold BN into weights/bias (per channel, redundant per thread, cheap)
    const float s1 = dw1_g[c] * rsqrtf(dw1_v[c] + 1e-5f);
    const float s2 = dw2_g[c] * rsqrtf(dw2_v[c] + 1e-5f);
    const float bb1 = dw1_b[c] - dw1_m[c] * s1;
    const float bb2 = dw2_b[c] - dw2_m[c] * s2;
    float w1[9], w2[9];
#pragma unroll
    for (int j = 0; j < 9; j++) {
        w1[j] = dw1_w[c * 9 + j] * s1;
        w2[j] = dw2_w[c * 9 + j] * s2;
    }
    __syncthreads();

    if (tid < 392) {
        const int row = tid / 7;
        const int cg = tid - row * 7;
        float a1[8], a2[8];
#pragma unroll
        for (int j = 0; j < 8; j++) { a1[j] = 0.f; a2[j] = 0.f; }
#pragma unroll
        for (int ky = 0; ky < 3; ky++) {
            const float* rp = &s[(row + ky) * 60 + cg * 8];
            float xr[10];
#pragma unroll
            for (int t = 0; t < 10; t++) xr[t] = rp[t];
#pragma unroll
            for (int kx = 0; kx < 3; kx++) {
                const float wa = w1[ky * 3 + kx];
                const float wb = w2[ky * 3 + kx];
#pragma unroll
                for (int j = 0; j < 8; j++) {
                    a1[j] += wa * xr[j + kx];
                    a2[j] += wb * xr[j + kx];
                }
            }
        }
        float f[8];
        float rsum = 0.f;
#pragma unroll
        for (int j = 0; j < 8; j++) {
            float a = a1[j] + bb1;
            a = fminf(fmaxf(a, 0.f), 6.f);
            float v = a * (a2[j] + bb2);
            f[j] = v;
            rsum += v;
        }
        float4* op = (float4*)(g_xfuse + (size_t)blk * PLANE + row * 56 + cg * 8);
        op[0] = make_float4(f[0], f[1], f[2], f[3]);
        op[1] = make_float4(f[4], f[5], f[6], f[7]);
        partial[tid] = rsum;
    }
    __syncthreads();

    if (tid < 49) {
        const int pr = tid / 7, pc = tid - pr * 7;
        float sm = 0.f;
#pragma unroll
        for (int i = 0; i < 8; i++) sm += partial[(pr * 8 + i) * 7 + pc];
        g_pooled[(b * 49 + tid) * NC + c] = sm * (1.f / 64.f);
    }
}

// ---------------------------------------------------------------------------
// Kernel 2: projection MLP + softmax over G -> w_dyn / b_dyn
// grid (50, B): pos 0..48 -> w_dyn at that position, pos 49 -> b_dyn (mean)
// ---------------------------------------------------------------------------
__global__ __launch_bounds__(256) void k_dyn(
    const float* __restrict__ pb1, const float* __restrict__ pb2,
    const float* __restrict__ bias1) {
    __shared__ float v[256];
    __shared__ float red[256];
    __shared__ float hsm[64];

    const int pos = blockIdx.x;
    const int b = blockIdx.y;
    const int t = threadIdx.x;

    if (pos < 49) {
        v[t] = g_pooled[(b * 49 + pos) * NC + t];
    } else {
        float sm = 0.f;
#pragma unroll
        for (int p = 0; p < 49; p++) sm += g_pooled[(b * 49 + p) * NC + t];
        v[t] = sm * (1.f / 49.f);
    }
    __syncthreads();

    // stage 1: h = gelu(pw1 @ v + pb1); 4 partial-threads per output
    {
        const int o = t & 63, part = t >> 6;
        float acc = 0.f;
        const int k0 = part * 64;
#pragma unroll 16
        for (int k = 0; k < 64; k++) acc += g_pw1T[(k0 + k) * 64 + o] * v[k0 + k];
        red[t] = acc;
    }
    __syncthreads();
    if (t < 64) {
        float x = red[t] + red[64 + t] + red[128 + t] + red[192 + t] + pb1[t];
        hsm[t] = 0.5f * x * (1.f + erff(x * 0.70710678118654752f));
    }
    __syncthreads();

    // stage 2: per channel c = t, compute the G=4 group logits, softmax locally
    float sg[4];
#pragma unroll
    for (int g = 0; g < 4; g++) {
        float a = pb2[g * 256 + t];
#pragma unroll 16
        for (int k = 0; k < 64; k++) a += g_pw2T[k * 1024 + g * 256 + t] * hsm[k];
        sg[g] = a;
    }
    float m = fmaxf(fmaxf(sg[0], sg[1]), fmaxf(sg[2], sg[3]));
    float e[4], se = 0.f;
#pragma unroll
    for (int g = 0; g < 4; g++) { e[g] = expf(sg[g] - m); se += e[g]; }
    const float inv = 1.f / se;

    if (pos < 49) {
        float wv = 0.f;
#pragma unroll
        for (int g = 0; g < 4; g++) wv += e[g] * inv * g_w1T[pos * 1024 + g * 256 + t];
        g_wdyn[(b * 49 + pos) * NC + t] = wv;
    } else {
        float bv = 0.f;
#pragma unroll
        for (int g = 0; g < 4; g++) bv += e[g] * inv * bias1[g * 256 + t];
        g_bdyn[b * NC + t] = bv;
    }
}

// ---------------------------------------------------------------------------
// Kernel 3: per-sample dynamic 7x7 depthwise conv + dynamic bias
// One block per (b,c) plane. 392 compute threads, 8 outputs each.
// ---------------------------------------------------------------------------
__global__ __launch_bounds__(448) void k_conv(float* __restrict__ out) {
    __shared__ float s[62 * 65];          // padded plane (halo=3), stride 65
    __shared__ float wsm[49];
    __shared__ float bsm;

    const int blk = blockIdx.x;
    const int b = blk >> 8, c = blk & 255;
    const float* __restrict__ xp = g_xfuse + (size_t)blk * PLANE;
    const int tid = threadIdx.x;

    for (int i = tid; i < 62 * 65; i += 448) {
        int r = i / 65, cc = i - r * 65;
        float v = 0.f;
        if (cc < 62) {
            int gr = r - 3, gc = cc - 3;
            if ((unsigned)gr < 56u && (unsigned)gc < 56u) v = xp[gr * 56 + gc];
        }
        s[i] = v;
    }
    if (tid < 49) wsm[tid] = g_wdyn[(b * 49 + tid) * NC + c];
    if (tid == 63) bsm = g_bdyn[b * NC + c];
    __syncthreads();

    if (tid < 392) {
        const int row = tid / 7;
        const int cg = tid - row * 7;
        float acc[8];
#pragma unroll
        for (int j = 0; j < 8; j++) acc[j] = 0.f;
#pragma unroll
        for (int ky = 0; ky < 7; ky++) {
            const float* rp = &s[(row + ky) * 65 + cg * 8];
            float xr[14];
#pragma unroll
            for (int t = 0; t < 14; t++) xr[t] = rp[t];
#pragma unroll
            for (int kx = 0; kx < 7; kx++) {
                const float wv = wsm[ky * 7 + kx];
#pragma unroll
                for (int j = 0; j < 8; j++) acc[j] += wv * xr[j + kx];
            }
        }
        const float bv = bsm;
        float4* op = (float4*)(out + (size_t)blk * PLANE + row * 56 + cg * 8);
        op[0] = make_float4(acc[0] + bv, acc[1] + bv, acc[2] + bv, acc[3] + bv);
        op[1] = make_float4(acc[4] + bv, acc[5] + bv, acc[6] + bv, acc[7] + bv);
    }
}

// ---------------------------------------------------------------------------
extern "C" void kernel_launch(void* const* d_in, const int* in_sizes, int n_in,
                              void* d_out, int out_size) {
    const float* x1    = (const float*)d_in[0];
    const float* dw1_w = (const float*)d_in[1];
    const float* dw1_g = (const float*)d_in[2];
    const float* dw1_b = (const float*)d_in[3];
    const float* dw1_m = (const float*)d_in[4];
    const float* dw1_v = (const float*)d_in[5];
    const float* dw2_w = (const float*)d_in[6];
    const float* dw2_g = (const float*)d_in[7];
    const float* dw2_b = (const float*)d_in[8];
    const float* dw2_m = (const float*)d_in[9];
    const float* dw2_v = (const float*)d_in[10];
    const float* weight1 = (const float*)d_in[11];
    const float* bias1   = (const float*)d_in[12];
    const float* pw1 = (const float*)d_in[13];
    const float* pb1 = (const float*)d_in[14];
    const float* pw2 = (const float*)d_in[15];
    const float* pb2 = (const float*)d_in[16];
    float* out = (float*)d_out;

    k_transpose<<<516, 256>>>(pw1, pw2, weight1);
    k_fuse<<<NPLANES, 448>>>(x1, dw1_w, dw1_g, dw1_b, dw1_m, dw1_v,
                             dw2_w, dw2_g, dw2_b, dw2_m, dw2_v);
    k_dyn<<<dim3(50, NB), 256>>>(pb1, pb2, bias1);
    k_conv<<<NPLANES, 448>>>(out);
}

// round 4
// speedup vs baseline: 1.5282x; 1.5282x over previous
#include <cuda_runtime.h>
#include <math.h>

#define NB 16
#define NC 256
#define PLANE 3136
#define NPLANES 4096
typedef unsigned long long ull;

// scratch (static device globals; no allocation)
__device__ float g_xfuse[NPLANES * PLANE];   // 51.4 MB
__device__ float g_pooled[NB * 49 * NC];     // [B][pos][C]
__device__ float g_wdyn[NB * 49 * NC];       // [B][pos][C]
__device__ float g_bdyn[NB * NC];            // [B][C]
__device__ float g_pw1T[256 * 64];           // [k][o]
__device__ float g_pw2T[64 * 1024];          // [k][oc]
__device__ float g_w1T[49 * 1024];           // [pos][g*C+c]

__device__ __forceinline__ void ffma2(ull& d, ull a, ull b) {
    asm("fma.rn.f32x2 %0, %1, %2, %0;" : "+l"(d) : "l"(a), "l"(b));
}
__device__ __forceinline__ float2 u2f2(ull v) {
    float2 r;
    r.x = __uint_as_float((unsigned)v);
    r.y = __uint_as_float((unsigned)(v >> 32));
    return r;
}

// ---------------------------------------------------------------------------
// Kernel 1: fused dw3x3+BN (x2), relu6 gate, x_fuse, 7x7 block-mean pool.
// Blocks >= NPLANES instead perform the small weight transposes.
// ---------------------------------------------------------------------------
__global__ __launch_bounds__(448, 3) void k_fuse(
    const float* __restrict__ x1,
    const float* __restrict__ dw1_w, const float* __restrict__ dw1_g,
    const float* __restrict__ dw1_b, const float* __restrict__ dw1_m,
    const float* __restrict__ dw1_v,
    const float* __restrict__ dw2_w, const float* __restrict__ dw2_g,
    const float* __restrict__ dw2_b, const float* __restrict__ dw2_m,
    const float* __restrict__ dw2_v,
    const float* __restrict__ pw1, const float* __restrict__ pw2,
    const float* __restrict__ w1grp) {
    const int tid = threadIdx.x;

    if (blockIdx.x >= NPLANES) {           // transpose side-work
        int i = (blockIdx.x - NPLANES) * 448 + tid;
        if (i < 16384) {                   // pw1 [64,256] -> [256,64]
            int k = i >> 6, o = i & 63;
            g_pw1T[i] = pw1[o * 256 + k];
        } else if (i < 81920) {            // pw2 [1024,64] -> [64,1024]
            int j = i - 16384;
            int k = j >> 10, oc = j & 1023;
            g_pw2T[j] = pw2[oc * 64 + k];
        } else if (i < 132096) {           // weight1 [G*C,49] -> [49,G*C]
            int l = i - 81920;
            int pos = l / 1024, gc = l & 1023;
            g_w1T[l] = w1grp[gc * 49 + pos];
        }
        return;
    }

    __shared__ float s[58 * 60];           // tile, halo 1, stride 60 (8B ok)
    __shared__ float2 sw1[9], sw2[9];      // packed (w,w) weights
    __shared__ float partial[392];

    const int blk = blockIdx.x;
    const int b = blk >> 8, c = blk & 255;

    // halo zeroing (rows 0,57 x 0..57; rows 1..56 x in {0,57}); interior f4
    if (tid < 228) {
        if (tid < 116) {
            int r = (tid < 58) ? 0 : 57;
            int x = (tid < 58) ? tid : tid - 58;
            s[r * 60 + x] = 0.f;
        } else {
            int j = tid - 116;
            int r = 1 + (j >> 1);
            int x = (j & 1) ? 57 : 0;
            s[r * 60 + x] = 0.f;
        }
    }
    {
        const float4* __restrict__ xp4 =
            (const float4*)(x1 + (size_t)blk * PLANE);
        for (int idx = tid; idx < 784; idx += 448) {
            int r = idx / 14, c4 = idx - r * 14;
            float4 v = xp4[idx];
            float* d = &s[(r + 1) * 60 + 1 + c4 * 4];
            d[0] = v.x; d[1] = v.y; d[2] = v.z; d[3] = v.w;
        }
    }
    // BN-folded channel scalars
    const float s1 = dw1_g[c] * rsqrtf(dw1_v[c] + 1e-5f);
    const float s2 = dw2_g[c] * rsqrtf(dw2_v[c] + 1e-5f);
    const float bb1 = dw1_b[c] - dw1_m[c] * s1;
    const float bb2 = dw2_b[c] - dw2_m[c] * s2;
    if (tid < 9) {
        float wa = dw1_w[c * 9 + tid] * s1;
        float wb = dw2_w[c * 9 + tid] * s2;
        sw1[tid] = make_float2(wa, wa);
        sw2[tid] = make_float2(wb, wb);
    }
    __syncthreads();

    if (tid < 392) {
        const int row = tid / 7;
        const int cg = tid - row * 7;
        ull aA[4] = {0, 0, 0, 0}, aB[4] = {0, 0, 0, 0};
#pragma unroll
        for (int ky = 0; ky < 3; ky++) {
            const float* rp = &s[(row + ky) * 60 + cg * 8];
            ull pe[5];
#pragma unroll
            for (int k = 0; k < 5; k++) pe[k] = *(const ull*)(rp + 2 * k);
            ull po[4];
#pragma unroll
            for (int m = 0; m < 4; m++)
                po[m] = (pe[m] >> 32) | (pe[m + 1] << 32);
#pragma unroll
            for (int t = 0; t < 2; t++) {   // kx = 0, 2
                ull wa = *(const ull*)&sw1[ky * 3 + 2 * t];
                ull wb = *(const ull*)&sw2[ky * 3 + 2 * t];
#pragma unroll
                for (int j = 0; j < 4; j++) {
                    ffma2(aA[j], wa, pe[j + t]);
                    ffma2(aB[j], wb, pe[j + t]);
                }
            }
            {                               // kx = 1
                ull wa = *(const ull*)&sw1[ky * 3 + 1];
                ull wb = *(const ull*)&sw2[ky * 3 + 1];
#pragma unroll
                for (int j = 0; j < 4; j++) {
                    ffma2(aA[j], wa, po[j]);
                    ffma2(aB[j], wb, po[j]);
                }
            }
        }
        float f[8];
        float rsum = 0.f;
#pragma unroll
        for (int j = 0; j < 4; j++) {
            float2 pa = u2f2(aA[j]), pb = u2f2(aB[j]);
            float a0 = fminf(fmaxf(pa.x + bb1, 0.f), 6.f);
            float a1 = fminf(fmaxf(pa.y + bb1, 0.f), 6.f);
            float v0 = a0 * (pb.x + bb2);
            float v1 = a1 * (pb.y + bb2);
            f[2 * j] = v0; f[2 * j + 1] = v1;
            rsum += v0 + v1;
        }
        float4* op = (float4*)(g_xfuse + (size_t)blk * PLANE + row * 56 + cg * 8);
        op[0] = make_float4(f[0], f[1], f[2], f[3]);
        op[1] = make_float4(f[4], f[5], f[6], f[7]);
        partial[tid] = rsum;
    }
    __syncthreads();

    if (tid < 49) {
        const int pr = tid / 7, pc = tid - pr * 7;
        float sm = 0.f;
#pragma unroll
        for (int i = 0; i < 8; i++) sm += partial[(pr * 8 + i) * 7 + pc];
        g_pooled[(b * 49 + tid) * NC + c] = sm * (1.f / 64.f);
    }
}

// ---------------------------------------------------------------------------
// Kernel 2: projection MLP + softmax over G -> w_dyn / b_dyn
// ---------------------------------------------------------------------------
__global__ __launch_bounds__(256) void k_dyn(
    const float* __restrict__ pb1, const float* __restrict__ pb2,
    const float* __restrict__ bias1) {
    __shared__ float v[256];
    __shared__ float red[256];
    __shared__ float hsm[64];

    const int pos = blockIdx.x;
    const int b = blockIdx.y;
    const int t = threadIdx.x;

    if (pos < 49) {
        v[t] = g_pooled[(b * 49 + pos) * NC + t];
    } else {
        float sm = 0.f;
#pragma unroll
        for (int p = 0; p < 49; p++) sm += g_pooled[(b * 49 + p) * NC + t];
        v[t] = sm * (1.f / 49.f);
    }
    __syncthreads();

    {
        const int o = t & 63, part = t >> 6;
        float acc = 0.f;
        const int k0 = part * 64;
#pragma unroll 16
        for (int k = 0; k < 64; k++) acc += g_pw1T[(k0 + k) * 64 + o] * v[k0 + k];
        red[t] = acc;
    }
    __syncthreads();
    if (t < 64) {
        float x = red[t] + red[64 + t] + red[128 + t] + red[192 + t] + pb1[t];
        hsm[t] = 0.5f * x * (1.f + erff(x * 0.70710678118654752f));
    }
    __syncthreads();

    float sg[4];
#pragma unroll
    for (int g = 0; g < 4; g++) {
        float a = pb2[g * 256 + t];
#pragma unroll 16
        for (int k = 0; k < 64; k++) a += g_pw2T[k * 1024 + g * 256 + t] * hsm[k];
        sg[g] = a;
    }
    float m = fmaxf(fmaxf(sg[0], sg[1]), fmaxf(sg[2], sg[3]));
    float e[4], se = 0.f;
#pragma unroll
    for (int g = 0; g < 4; g++) { e[g] = expf(sg[g] - m); se += e[g]; }
    const float inv = 1.f / se;

    if (pos < 49) {
        float wv = 0.f;
#pragma unroll
        for (int g = 0; g < 4; g++) wv += e[g] * inv * g_w1T[pos * 1024 + g * 256 + t];
        g_wdyn[(b * 49 + pos) * NC + t] = wv;
    } else {
        float bv = 0.f;
#pragma unroll
        for (int g = 0; g < 4; g++) bv += e[g] * inv * bias1[g * 256 + t];
        g_bdyn[b * NC + t] = bv;
    }
}

// ---------------------------------------------------------------------------
// Kernel 3: per-sample dynamic 7x7 depthwise conv + dynamic bias (f32x2)
// ---------------------------------------------------------------------------
__global__ __launch_bounds__(448, 3) void k_conv(float* __restrict__ out) {
    __shared__ float s[62 * 66];           // tile, halo 3, stride 66 (8B ok)
    __shared__ float2 wsm2[49];            // packed (w,w)
    __shared__ float bsm;

    const int blk = blockIdx.x;
    const int b = blk >> 8, c = blk & 255;
    const int tid = threadIdx.x;

    // halo zeroing: rows {0,1,2,59,60,61} full + rows 3..58 x in {0,1,2,59,60,61}
    // 708 halo cells total; block has 448 threads -> MUST loop (R2 bug fix).
    for (int i = tid; i < 708; i += 448) {
        if (i < 372) {
            int rr = i / 62, x = i - rr * 62;
            int r = (rr < 3) ? rr : 56 + rr;
            s[r * 66 + x] = 0.f;
        } else {
            int j = i - 372;
            int rr = 3 + j / 6, xs = j - (j / 6) * 6;
            int x = (xs < 3) ? xs : 56 + xs;
            s[rr * 66 + x] = 0.f;
        }
    }
    {
        const float4* __restrict__ xp4 =
            (const float4*)(g_xfuse + (size_t)blk * PLANE);
        for (int idx = tid; idx < 784; idx += 448) {
            int r = idx / 14, c4 = idx - r * 14;
            float4 v = xp4[idx];
            float* d = &s[(r + 3) * 66 + 3 + c4 * 4];
            d[0] = v.x; d[1] = v.y; d[2] = v.z; d[3] = v.w;
        }
    }
    if (tid < 49) {
        float w = g_wdyn[(b * 49 + tid) * NC + c];
        wsm2[tid] = make_float2(w, w);
    }
    if (tid == 63) bsm = g_bdyn[b * NC + c];
    __syncthreads();

    if (tid < 392) {
        const int row = tid / 7;
        const int cg = tid - row * 7;
        ull acc[4] = {0, 0, 0, 0};
#pragma unroll
        for (int ky = 0; ky < 7; ky++) {
            const float* rp = &s[(row + ky) * 66 + cg * 8];
            ull pe[7];
#pragma unroll
            for (int k = 0; k < 7; k++) pe[k] = *(const ull*)(rp + 2 * k);
            ull po[6];
#pragma unroll
            for (int m = 0; m < 6; m++)
                po[m] = (pe[m] >> 32) | (pe[m + 1] << 32);
#pragma unroll
            for (int t = 0; t < 4; t++) {   // kx = 0,2,4,6
                ull w = *(const ull*)&wsm2[ky * 7 + 2 * t];
#pragma unroll
                for (int j = 0; j < 4; j++) ffma2(acc[j], w, pe[j + t]);
            }
#pragma unroll
            for (int t = 0; t < 3; t++) {   // kx = 1,3,5
                ull w = *(const ull*)&wsm2[ky * 7 + 2 * t + 1];
#pragma unroll
                for (int j = 0; j < 4; j++) ffma2(acc[j], w, po[j + t]);
            }
        }
        const float bv = bsm;
        float2 p0 = u2f2(acc[0]), p1 = u2f2(acc[1]);
        float2 p2 = u2f2(acc[2]), p3 = u2f2(acc[3]);
        float4* op = (float4*)(out + (size_t)blk * PLANE + row * 56 + cg * 8);
        op[0] = make_float4(p0.x + bv, p0.y + bv, p1.x + bv, p1.y + bv);
        op[1] = make_float4(p2.x + bv, p2.y + bv, p3.x + bv, p3.y + bv);
    }
}

// ---------------------------------------------------------------------------
extern "C" void kernel_launch(void* const* d_in, const int* in_sizes, int n_in,
                              void* d_out, int out_size) {
    const float* x1    = (const float*)d_in[0];
    const float* dw1_w = (const float*)d_in[1];
    const float* dw1_g = (const float*)d_in[2];
    const float* dw1_b = (const float*)d_in[3];
    const float* dw1_m = (const float*)d_in[4];
    const float* dw1_v = (const float*)d_in[5];
    const float* dw2_w = (const float*)d_in[6];
    const float* dw2_g = (const float*)d_in[7];
    const float* dw2_b = (const float*)d_in[8];
    const float* dw2_m = (const float*)d_in[9];
    const float* dw2_v = (const float*)d_in[10];
    const float* weight1 = (const float*)d_in[11];
    const float* bias1   = (const float*)d_in[12];
    const float* pw1 = (const float*)d_in[13];
    const float* pb1 = (const float*)d_in[14];
    const float* pw2 = (const float*)d_in[15];
    const float* pb2 = (const float*)d_in[16];
    float* out = (float*)d_out;

    k_fuse<<<NPLANES + 295, 448>>>(x1, dw1_w, dw1_g, dw1_b, dw1_m, dw1_v,
                                   dw2_w, dw2_g, dw2_b, dw2_m, dw2_v,
                                   pw1, pw2, weight1);
    k_dyn<<<dim3(50, NB), 256>>>(pb1, pb2, bias1);
    k_conv<<<NPLANES, 448>>>(out);
}